// round 16
// baseline (speedup 1.0000x reference)
#include <cuda_runtime.h>
#include <cuda_fp16.h>

#define B_SZ 2
#define T_SEQ 2048
#define C_DIM 1024
#define NH 16
#define HD 64
#define N_QKV 3072

typedef unsigned int u32;

#define QKV_ELEMS ((size_t)B_SZ*NH*T_SEQ*HD)
__device__ __half g_qh[QKV_ELEMS];
__device__ __half g_kh[QKV_ELEMS];
__device__ __half g_vh[QKV_ELEMS];
__device__ __half g_yh[QKV_ELEMS];

__device__ __forceinline__ u32 pack2h(float x, float y){
    u32 a = (u32)__half_as_ushort(__float2half_rn(x));
    u32 b = (u32)__half_as_ushort(__float2half_rn(y));
    return a | (b<<16);
}
__device__ __forceinline__ void mma_f16(float* d, const u32* a, u32 b0, u32 b1){
    asm volatile("mma.sync.aligned.m16n8k16.row.col.f32.f16.f16.f32 "
      "{%0,%1,%2,%3},{%4,%5,%6,%7},{%8,%9},{%0,%1,%2,%3};\n"
      : "+f"(d[0]),"+f"(d[1]),"+f"(d[2]),"+f"(d[3])
      : "r"(a[0]),"r"(a[1]),"r"(a[2]),"r"(a[3]),"r"(b0),"r"(b1));
}
__device__ __forceinline__ void ldm4(u32* r, const __half* p){
    u32 sa = (u32)__cvta_generic_to_shared(p);
    asm volatile("ldmatrix.sync.aligned.m8n8.x4.shared.b16 {%0,%1,%2,%3},[%4];"
      : "=r"(r[0]),"=r"(r[1]),"=r"(r[2]),"=r"(r[3]) : "r"(sa));
}
__device__ __forceinline__ u32 prmt(u32 a, u32 b, u32 sel){
    u32 r; asm("prmt.b32 %0,%1,%2,%3;" : "=r"(r) : "r"(a),"r"(b),"r"(sel));
    return r;
}

// ---------------------------------------------------------------------------
// GEMM: 128x256 block tile, KB=16, 8 warps, 64x64 warp tile (acc 128 regs),
// register-staged prefetch. 125 B smem traffic per MMA (2x reuse vs 32x32).
// MODE0: fp16(x) @ fp16(W_qkv) + b -> q(x0.125)/k/v fp16.
// MODE1: y(fp16) @ fp16(W_out) + b -> fp32 out.
// ---------------------------------------------------------------------------
#define SA2 24
#define SBX 264

template<int MODE>
__global__ __launch_bounds__(256) void gemm_kernel(
    const float* __restrict__ Afp, const float* __restrict__ W,
    const float* __restrict__ bias, float* __restrict__ outp)
{
    const int N = (MODE==0) ? N_QKV : C_DIM;
    __shared__ __half Ah[128*SA2];
    __shared__ u32    Bh[8*SBX];

    int tid = threadIdx.x, lane = tid&31, wid = tid>>5;
    int g = lane>>2, c = lane&3;
    int row0 = blockIdx.y*128, col0 = blockIdx.x*256;
    int wm = (wid>>2)*64, wn = (wid&3)*64;

    float acc[4][8][4];
    #pragma unroll
    for (int i=0;i<4;i++)
        #pragma unroll
        for (int j=0;j<8;j++)
            #pragma unroll
            for (int q=0;q<4;q++) acc[i][j][q] = 0.f;

    // register staging (one k-tile ahead)
    float4 ra0, ra1;
    uint4  rah;
    float4 rb[4];

    const int ar = tid>>1, akq = (tid&1)*8;
    const int bkp = tid>>5, bn0 = (tid&31)*8;

    auto ldg = [&](int k0){
        if (MODE==0) {
            const float* p = Afp + (size_t)(row0+ar)*C_DIM + k0+akq;
            ra0 = *(const float4*)p;
            ra1 = *(const float4*)(p+4);
        } else {
            rah = *(const uint4*)(g_yh + (size_t)(row0+ar)*C_DIM + k0+akq);
        }
        {
            const float* p0 = W + (size_t)(k0+2*bkp)*N + col0+bn0;
            rb[0] = *(const float4*)p0;
            rb[1] = *(const float4*)(p0+4);
            rb[2] = *(const float4*)(p0+N);
            rb[3] = *(const float4*)(p0+N+4);
        }
    };
    auto sts = [&](){
        if (MODE==0) {
            u32 h0 = pack2h(ra0.x, ra0.y), h1 = pack2h(ra0.z, ra0.w);
            u32 h2 = pack2h(ra1.x, ra1.y), h3 = pack2h(ra1.z, ra1.w);
            *(uint2*)(Ah + ar*SA2 + akq)     = make_uint2(h0,h1);
            *(uint2*)(Ah + ar*SA2 + akq + 4) = make_uint2(h2,h3);
        } else {
            *(uint4*)(Ah + ar*SA2 + akq) = rah;
        }
        {
            u32 hh[8];
            hh[0] = pack2h(rb[0].x, rb[2].x);
            hh[1] = pack2h(rb[0].y, rb[2].y);
            hh[2] = pack2h(rb[0].z, rb[2].z);
            hh[3] = pack2h(rb[0].w, rb[2].w);
            hh[4] = pack2h(rb[1].x, rb[3].x);
            hh[5] = pack2h(rb[1].y, rb[3].y);
            hh[6] = pack2h(rb[1].z, rb[3].z);
            hh[7] = pack2h(rb[1].w, rb[3].w);
            *(uint4*)(Bh + bkp*SBX + bn0)     = make_uint4(hh[0],hh[1],hh[2],hh[3]);
            *(uint4*)(Bh + bkp*SBX + bn0 + 4) = make_uint4(hh[4],hh[5],hh[6],hh[7]);
        }
    };

    ldg(0); sts(); __syncthreads();

    for (int k0=0; k0<C_DIM; k0+=16) {
        if (k0+16 < C_DIM) ldg(k0+16);   // prefetch next tile into registers

        u32 ah[4][4];
        #pragma unroll
        for (int mt=0;mt<4;mt++){
            int r = wm + mt*16 + (lane&7) + ((lane>>3)&1)*8;
            int cc = (lane>>4)*8;
            ldm4(ah[mt], Ah + r*SA2 + cc);
        }
        #pragma unroll
        for (int nt=0;nt<8;nt++){
            int bi = c*SBX + wn + nt*8 + g;
            u32 b0 = Bh[bi], b1 = Bh[bi + 4*SBX];
            #pragma unroll
            for (int mt=0;mt<4;mt++)
                mma_f16(acc[mt][nt], ah[mt], b0, b1);
        }
        __syncthreads();
        if (k0+16 < C_DIM){ sts(); __syncthreads(); }
    }

    #pragma unroll
    for (int mt=0;mt<4;mt++){
        int rg = row0 + wm + mt*16 + g;
        #pragma unroll
        for (int nt=0;nt<8;nt++){
            int jc = col0 + wn + nt*8 + 2*c;
            float bv0 = bias[jc], bv1 = bias[jc+1];
            float v00 = acc[mt][nt][0]+bv0, v01 = acc[mt][nt][1]+bv1;
            float v10 = acc[mt][nt][2]+bv0, v11 = acc[mt][nt][3]+bv1;
            if (MODE==0) {
                int part = jc>>10, cc2 = jc&1023, h = cc2>>6, d = cc2&63;
                int rr[2] = {rg, rg+8};
                float va[2][2] = {{v00,v01},{v10,v11}};
                #pragma unroll
                for (int ii=0;ii<2;ii++){
                    int t = rr[ii]&2047, bb = rr[ii]>>11;
                    size_t idx = (((size_t)(bb*NH+h))*T_SEQ + t)*HD + d;
                    if (part==0)
                        *(u32*)(g_qh+idx) = pack2h(va[ii][0]*0.125f, va[ii][1]*0.125f);
                    else if (part==1)
                        *(u32*)(g_kh+idx) = pack2h(va[ii][0], va[ii][1]);
                    else
                        *(u32*)(g_vh+idx) = pack2h(va[ii][0], va[ii][1]);
                }
            } else {
                *(float2*)(outp + (size_t)rg*C_DIM + jc)     = make_float2(v00,v01);
                *(float2*)(outp + (size_t)(rg+8)*C_DIM + jc) = make_float2(v10,v11);
            }
        }
    }
}

// ---------------------------------------------------------------------------
// Flash attention: straight fp16 1-term (Q, K, V, P fp16), K/V register
// prefetch, 2 CTAs/SM, heavy-tile-first. (Byte-identical to R15.)
// ---------------------------------------------------------------------------
#define SK 36

__global__ __launch_bounds__(256,2) void attn_kernel()
{
    __shared__ u32 Kph[64*SK], Vph[64*SK];

    int tid = threadIdx.x, lane = tid&31, wid = tid>>5;
    int g = lane>>2, c = lane&3;
    int qt = (gridDim.y - 1) - blockIdx.y;   // heaviest q-tiles launch first
    int bh = blockIdx.x;
    int b = bh>>4, h = bh&15;
    size_t base = (size_t)bh * T_SEQ * HD;
    int Q0 = qt*128, wrow = wid*16;

    u32 qh[4][4];
    #pragma unroll
    for (int kc=0;kc<4;kc++){
        size_t i00 = base + (size_t)(Q0+wrow+g)*HD + kc*16 + 2*c;
        size_t i10 = i00 + 8ull*HD;
        qh[kc][0] = *(const u32*)(g_qh+i00); qh[kc][1] = *(const u32*)(g_qh+i10);
        qh[kc][2] = *(const u32*)(g_qh+i00+8); qh[kc][3] = *(const u32*)(g_qh+i10+8);
    }

    float m0=-1e30f, m1=-1e30f, l0=0.f, l1=0.f;
    float o[8][4];
    #pragma unroll
    for (int i=0;i<8;i++){ o[i][0]=0.f; o[i][1]=0.f; o[i][2]=0.f; o[i][3]=0.f; }

    uint4 pk0, pk1;
    u32 pv[8];
    const int kidx = tid>>2, kq4 = tid&3;
    const int vkp = tid>>3, vdd = (tid&7)*8;

    auto ldg_kv = [&](int kt){
        int K0 = kt*64;
        size_t go = base + (size_t)(K0+kidx)*HD + kq4*16;
        pk0 = *(const uint4*)(g_kh+go);
        pk1 = *(const uint4*)(g_kh+go+8);
        size_t r0o = base + (size_t)(K0+2*vkp)*HD + vdd;
        const u32* ap = (const u32*)(g_vh + r0o);
        const u32* bp = (const u32*)(g_vh + r0o + HD);
        #pragma unroll
        for (int j=0;j<4;j++){ pv[j] = ap[j]; pv[4+j] = bp[j]; }
    };
    auto sts_kv = [&](){
        *(uint4*)(Kph + kidx*SK + kq4*8)     = pk0;
        *(uint4*)(Kph + kidx*SK + kq4*8 + 4) = pk1;
        #pragma unroll
        for (int j=0;j<4;j++){
            u32 x = pv[j], y = pv[4+j];
            Vph[(vdd+2*j)*SK + vkp]   = prmt(x,y,0x5410);
            Vph[(vdd+2*j+1)*SK + vkp] = prmt(x,y,0x7632);
        }
    };

    const int NKT = 2*qt+2;
    ldg_kv(0);

    for (int kt=0; kt<NKT; kt++){
        int K0 = kt*64;
        sts_kv();
        __syncthreads();
        if (kt+1 < NKT) ldg_kv(kt+1);

        float s[8][4];
        #pragma unroll
        for (int i=0;i<8;i++){ s[i][0]=0.f; s[i][1]=0.f; s[i][2]=0.f; s[i][3]=0.f; }
        #pragma unroll
        for (int kc=0;kc<4;kc++){
            #pragma unroll
            for (int nt=0;nt<8;nt++){
                int bi = (nt*8+g)*SK + kc*8 + c;
                u32 bh0 = Kph[bi], bh1 = Kph[bi+4];
                mma_f16(s[nt], qh[kc], bh0, bh1);
            }
        }

        if (kt >= 2*qt){
            int r0 = Q0+wrow+g, r1 = r0+8;
            #pragma unroll
            for (int nt=0;nt<8;nt++){
                int kk = K0 + nt*8 + 2*c;
                if (kk   > r0) s[nt][0] = -1e30f;
                if (kk+1 > r0) s[nt][1] = -1e30f;
                if (kk   > r1) s[nt][2] = -1e30f;
                if (kk+1 > r1) s[nt][3] = -1e30f;
            }
        }

        float tm0=-1e30f, tm1=-1e30f;
        #pragma unroll
        for (int nt=0;nt<8;nt++){
            tm0 = fmaxf(tm0, fmaxf(s[nt][0], s[nt][1]));
            tm1 = fmaxf(tm1, fmaxf(s[nt][2], s[nt][3]));
        }
        tm0 = fmaxf(tm0, __shfl_xor_sync(0xffffffffu, tm0, 1));
        tm0 = fmaxf(tm0, __shfl_xor_sync(0xffffffffu, tm0, 2));
        tm1 = fmaxf(tm1, __shfl_xor_sync(0xffffffffu, tm1, 1));
        tm1 = fmaxf(tm1, __shfl_xor_sync(0xffffffffu, tm1, 2));
        float nm0 = fmaxf(m0, tm0), nm1 = fmaxf(m1, tm1);
        float cor0 = __expf(m0-nm0), cor1 = __expf(m1-nm1);
        m0 = nm0; m1 = nm1;
        float ts0 = 0.f, ts1 = 0.f;
        #pragma unroll
        for (int nt=0;nt<8;nt++){
            s[nt][0] = __expf(s[nt][0]-nm0); ts0 += s[nt][0];
            s[nt][1] = __expf(s[nt][1]-nm0); ts0 += s[nt][1];
            s[nt][2] = __expf(s[nt][2]-nm1); ts1 += s[nt][2];
            s[nt][3] = __expf(s[nt][3]-nm1); ts1 += s[nt][3];
        }
        ts0 += __shfl_xor_sync(0xffffffffu, ts0, 1);
        ts0 += __shfl_xor_sync(0xffffffffu, ts0, 2);
        ts1 += __shfl_xor_sync(0xffffffffu, ts1, 1);
        ts1 += __shfl_xor_sync(0xffffffffu, ts1, 2);
        l0 = l0*cor0 + ts0; l1 = l1*cor1 + ts1;
        #pragma unroll
        for (int dt=0;dt<8;dt++){
            o[dt][0]*=cor0; o[dt][1]*=cor0; o[dt][2]*=cor1; o[dt][3]*=cor1;
        }

        #pragma unroll
        for (int kc=0;kc<4;kc++){
            u32 ph_[4];
            ph_[0] = pack2h(s[2*kc][0],   s[2*kc][1]);
            ph_[1] = pack2h(s[2*kc][2],   s[2*kc][3]);
            ph_[2] = pack2h(s[2*kc+1][0], s[2*kc+1][1]);
            ph_[3] = pack2h(s[2*kc+1][2], s[2*kc+1][3]);
            #pragma unroll
            for (int dt=0;dt<8;dt++){
                int bi = (dt*8+g)*SK + kc*8 + c;
                u32 vh0 = Vph[bi], vh1 = Vph[bi+4];
                mma_f16(o[dt], ph_, vh0, vh1);
            }
        }
        __syncthreads();
    }

    float i0 = 1.f/l0, i1 = 1.f/l1;
    size_t yb0 = ((size_t)(b*T_SEQ) + Q0+wrow+g)*C_DIM + h*HD;
    size_t yb1 = yb0 + 8ull*C_DIM;
    #pragma unroll
    for (int dt=0;dt<8;dt++){
        int dc = dt*8 + 2*c;
        *(u32*)(g_yh+yb0+dc) = pack2h(o[dt][0]*i0, o[dt][1]*i0);
        *(u32*)(g_yh+yb1+dc) = pack2h(o[dt][2]*i1, o[dt][3]*i1);
    }
}

// ---------------------------------------------------------------------------
extern "C" void kernel_launch(void* const* d_in, const int* in_sizes, int n_in,
                              void* d_out, int out_size)
{
    (void)in_sizes; (void)n_in; (void)out_size;
    const float* x     = (const float*)d_in[0];
    const float* W_qkv = (const float*)d_in[2];
    const float* b_qkv = (const float*)d_in[3];
    const float* W_out = (const float*)d_in[4];
    const float* b_out = (const float*)d_in[5];
    float* out = (float*)d_out;

    gemm_kernel<0><<<dim3(N_QKV/256, 4096/128), 256>>>(x, W_qkv, b_qkv, nullptr);
    attn_kernel<<<dim3(B_SZ*NH, T_SEQ/128), 256>>>();
    gemm_kernel<1><<<dim3(C_DIM/256, 4096/128), 256>>>(nullptr, W_out, b_out, out);
}

// round 17
// speedup vs baseline: 1.2883x; 1.2883x over previous
#include <cuda_runtime.h>
#include <cuda_fp16.h>

#define B_SZ 2
#define T_SEQ 2048
#define C_DIM 1024
#define NH 16
#define HD 64
#define N_QKV 3072

typedef unsigned int u32;

#define QKV_ELEMS ((size_t)B_SZ*NH*T_SEQ*HD)
__device__ __half g_qh[QKV_ELEMS];
__device__ __half g_kh[QKV_ELEMS];
__device__ __half g_vh[QKV_ELEMS];
__device__ __half g_yh[QKV_ELEMS];

__device__ __forceinline__ u32 pack2h(float x, float y){
    u32 a = (u32)__half_as_ushort(__float2half_rn(x));
    u32 b = (u32)__half_as_ushort(__float2half_rn(y));
    return a | (b<<16);
}
__device__ __forceinline__ void mma_f16(float* d, const u32* a, u32 b0, u32 b1){
    asm volatile("mma.sync.aligned.m16n8k16.row.col.f32.f16.f16.f32 "
      "{%0,%1,%2,%3},{%4,%5,%6,%7},{%8,%9},{%0,%1,%2,%3};\n"
      : "+f"(d[0]),"+f"(d[1]),"+f"(d[2]),"+f"(d[3])
      : "r"(a[0]),"r"(a[1]),"r"(a[2]),"r"(a[3]),"r"(b0),"r"(b1));
}
__device__ __forceinline__ void ldm4(u32* r, const __half* p){
    u32 sa = (u32)__cvta_generic_to_shared(p);
    asm volatile("ldmatrix.sync.aligned.m8n8.x4.shared.b16 {%0,%1,%2,%3},[%4];"
      : "=r"(r[0]),"=r"(r[1]),"=r"(r[2]),"=r"(r[3]) : "r"(sa));
}
__device__ __forceinline__ u32 prmt(u32 a, u32 b, u32 sel){
    u32 r; asm("prmt.b32 %0,%1,%2,%3;" : "=r"(r) : "r"(a),"r"(b),"r"(sel));
    return r;
}

// ---------------------------------------------------------------------------
// GEMM: 128x128 block tile, KB=32, 8 warps, 64x32 warp tile (acc 64 regs),
// packed register staging, 2 CTAs/SM. 187 B smem traffic per MMA.
// MODE0: fp16(x) @ fp16(W_qkv) + b -> q(x0.125)/k/v fp16.
// MODE1: y(fp16) @ fp16(W_out) + b -> fp32 out.
// ---------------------------------------------------------------------------
#define SA 40
#define SB 136

template<int MODE>
__global__ __launch_bounds__(256,2) void gemm_kernel(
    const float* __restrict__ Afp, const float* __restrict__ W,
    const float* __restrict__ bias, float* __restrict__ outp)
{
    const int N = (MODE==0) ? N_QKV : C_DIM;
    __shared__ __half Ah[128*SA];
    __shared__ u32    Bh[16*SB];

    int tid = threadIdx.x, lane = tid&31, wid = tid>>5;
    int g = lane>>2, c = lane&3;
    int row0 = blockIdx.y*128, col0 = blockIdx.x*128;
    int wm = (wid>>2)*64, wn = (wid&3)*32;

    float acc[4][4][4];
    #pragma unroll
    for (int i=0;i<4;i++)
        #pragma unroll
        for (int j=0;j<4;j++)
            #pragma unroll
            for (int q=0;q<4;q++) acc[i][j][q] = 0.f;

    // packed register staging (one k-tile ahead)
    u32  rap[8];      // MODE0: 8 packed u32 (16 halves)
    uint4 rayh[2];    // MODE1
    u32  rbp[8];

    auto ldg = [&](int k0){
        if (MODE==0) {
            #pragma unroll
            for (int i=0;i<4;i++){
                int e = i*256+tid; int r = e>>3, kq = (e&7)*4;
                float4 v = *(const float4*)(Afp + (size_t)(row0+r)*C_DIM + k0+kq);
                rap[2*i]   = pack2h(v.x, v.y);
                rap[2*i+1] = pack2h(v.z, v.w);
            }
        } else {
            #pragma unroll
            for (int i=0;i<2;i++){
                int e = i*256+tid; int r = e>>2, kq = (e&3)*8;
                rayh[i] = *(const uint4*)(g_yh + (size_t)(row0+r)*C_DIM + k0+kq);
            }
        }
        #pragma unroll
        for (int i=0;i<2;i++){
            int w = i*256+tid; int kp = w>>5, n0 = (w&31)*4;
            const float* p0 = W + (size_t)(k0+2*kp)*N + col0+n0;
            float4 r0 = *(const float4*)p0, r1 = *(const float4*)(p0+N);
            rbp[4*i+0] = pack2h(r0.x, r1.x);
            rbp[4*i+1] = pack2h(r0.y, r1.y);
            rbp[4*i+2] = pack2h(r0.z, r1.z);
            rbp[4*i+3] = pack2h(r0.w, r1.w);
        }
    };
    auto sts = [&](){
        if (MODE==0) {
            #pragma unroll
            for (int i=0;i<4;i++){
                int e = i*256+tid; int r = e>>3, kq = (e&7)*4;
                *(uint2*)(Ah + r*SA + kq) = make_uint2(rap[2*i], rap[2*i+1]);
            }
        } else {
            #pragma unroll
            for (int i=0;i<2;i++){
                int e = i*256+tid; int r = e>>2, kq = (e&3)*8;
                *(uint4*)(Ah + r*SA + kq) = rayh[i];
            }
        }
        #pragma unroll
        for (int i=0;i<2;i++){
            int w = i*256+tid; int kp = w>>5, n0 = (w&31)*4;
            *(uint4*)(Bh + kp*SB + n0) =
                make_uint4(rbp[4*i+0], rbp[4*i+1], rbp[4*i+2], rbp[4*i+3]);
        }
    };

    ldg(0); sts(); __syncthreads();

    for (int k0=0; k0<C_DIM; k0+=32) {
        if (k0+32 < C_DIM) ldg(k0+32);   // prefetch next tile into registers

        #pragma unroll
        for (int kc=0;kc<2;kc++){
            u32 ah[4][4];
            #pragma unroll
            for (int mt=0;mt<4;mt++){
                int r = wm + mt*16 + (lane&7) + ((lane>>3)&1)*8;
                int cc = kc*16 + (lane>>4)*8;
                ldm4(ah[mt], Ah + r*SA + cc);
            }
            #pragma unroll
            for (int nt=0;nt<4;nt++){
                int bi = (8*kc+c)*SB + wn + nt*8 + g;
                u32 b0 = Bh[bi], b1 = Bh[bi+4*SB];
                #pragma unroll
                for (int mt=0;mt<4;mt++)
                    mma_f16(acc[mt][nt], ah[mt], b0, b1);
            }
        }
        __syncthreads();
        if (k0+32 < C_DIM){ sts(); __syncthreads(); }
    }

    #pragma unroll
    for (int mt=0;mt<4;mt++){
        int rg = row0 + wm + mt*16 + g;
        #pragma unroll
        for (int nt=0;nt<4;nt++){
            int jc = col0 + wn + nt*8 + 2*c;
            float bv0 = bias[jc], bv1 = bias[jc+1];
            float v00 = acc[mt][nt][0]+bv0, v01 = acc[mt][nt][1]+bv1;
            float v10 = acc[mt][nt][2]+bv0, v11 = acc[mt][nt][3]+bv1;
            if (MODE==0) {
                int part = jc>>10, cc2 = jc&1023, h = cc2>>6, d = cc2&63;
                int rr[2] = {rg, rg+8};
                float va[2][2] = {{v00,v01},{v10,v11}};
                #pragma unroll
                for (int ii=0;ii<2;ii++){
                    int t = rr[ii]&2047, bb = rr[ii]>>11;
                    size_t idx = (((size_t)(bb*NH+h))*T_SEQ + t)*HD + d;
                    if (part==0)
                        *(u32*)(g_qh+idx) = pack2h(va[ii][0]*0.125f, va[ii][1]*0.125f);
                    else if (part==1)
                        *(u32*)(g_kh+idx) = pack2h(va[ii][0], va[ii][1]);
                    else
                        *(u32*)(g_vh+idx) = pack2h(va[ii][0], va[ii][1]);
                }
            } else {
                *(float2*)(outp + (size_t)rg*C_DIM + jc)     = make_float2(v00,v01);
                *(float2*)(outp + (size_t)(rg+8)*C_DIM + jc) = make_float2(v10,v11);
            }
        }
    }
}

// ---------------------------------------------------------------------------
// Flash attention: straight fp16 1-term (Q, K, V, P fp16), K/V register
// prefetch, 2 CTAs/SM, heavy-tile-first. (Byte-identical to R15.)
// ---------------------------------------------------------------------------
#define SK 36

__global__ __launch_bounds__(256,2) void attn_kernel()
{
    __shared__ u32 Kph[64*SK], Vph[64*SK];

    int tid = threadIdx.x, lane = tid&31, wid = tid>>5;
    int g = lane>>2, c = lane&3;
    int qt = (gridDim.y - 1) - blockIdx.y;   // heaviest q-tiles launch first
    int bh = blockIdx.x;
    int b = bh>>4, h = bh&15;
    size_t base = (size_t)bh * T_SEQ * HD;
    int Q0 = qt*128, wrow = wid*16;

    u32 qh[4][4];
    #pragma unroll
    for (int kc=0;kc<4;kc++){
        size_t i00 = base + (size_t)(Q0+wrow+g)*HD + kc*16 + 2*c;
        size_t i10 = i00 + 8ull*HD;
        qh[kc][0] = *(const u32*)(g_qh+i00); qh[kc][1] = *(const u32*)(g_qh+i10);
        qh[kc][2] = *(const u32*)(g_qh+i00+8); qh[kc][3] = *(const u32*)(g_qh+i10+8);
    }

    float m0=-1e30f, m1=-1e30f, l0=0.f, l1=0.f;
    float o[8][4];
    #pragma unroll
    for (int i=0;i<8;i++){ o[i][0]=0.f; o[i][1]=0.f; o[i][2]=0.f; o[i][3]=0.f; }

    uint4 pk0, pk1;
    u32 pv[8];
    const int kidx = tid>>2, kq4 = tid&3;
    const int vkp = tid>>3, vdd = (tid&7)*8;

    auto ldg_kv = [&](int kt){
        int K0 = kt*64;
        size_t go = base + (size_t)(K0+kidx)*HD + kq4*16;
        pk0 = *(const uint4*)(g_kh+go);
        pk1 = *(const uint4*)(g_kh+go+8);
        size_t r0o = base + (size_t)(K0+2*vkp)*HD + vdd;
        const u32* ap = (const u32*)(g_vh + r0o);
        const u32* bp = (const u32*)(g_vh + r0o + HD);
        #pragma unroll
        for (int j=0;j<4;j++){ pv[j] = ap[j]; pv[4+j] = bp[j]; }
    };
    auto sts_kv = [&](){
        *(uint4*)(Kph + kidx*SK + kq4*8)     = pk0;
        *(uint4*)(Kph + kidx*SK + kq4*8 + 4) = pk1;
        #pragma unroll
        for (int j=0;j<4;j++){
            u32 x = pv[j], y = pv[4+j];
            Vph[(vdd+2*j)*SK + vkp]   = prmt(x,y,0x5410);
            Vph[(vdd+2*j+1)*SK + vkp] = prmt(x,y,0x7632);
        }
    };

    const int NKT = 2*qt+2;
    ldg_kv(0);

    for (int kt=0; kt<NKT; kt++){
        int K0 = kt*64;
        sts_kv();
        __syncthreads();
        if (kt+1 < NKT) ldg_kv(kt+1);

        float s[8][4];
        #pragma unroll
        for (int i=0;i<8;i++){ s[i][0]=0.f; s[i][1]=0.f; s[i][2]=0.f; s[i][3]=0.f; }
        #pragma unroll
        for (int kc=0;kc<4;kc++){
            #pragma unroll
            for (int nt=0;nt<8;nt++){
                int bi = (nt*8+g)*SK + kc*8 + c;
                u32 bh0 = Kph[bi], bh1 = Kph[bi+4];
                mma_f16(s[nt], qh[kc], bh0, bh1);
            }
        }

        if (kt >= 2*qt){
            int r0 = Q0+wrow+g, r1 = r0+8;
            #pragma unroll
            for (int nt=0;nt<8;nt++){
                int kk = K0 + nt*8 + 2*c;
                if (kk   > r0) s[nt][0] = -1e30f;
                if (kk+1 > r0) s[nt][1] = -1e30f;
                if (kk   > r1) s[nt][2] = -1e30f;
                if (kk+1 > r1) s[nt][3] = -1e30f;
            }
        }

        float tm0=-1e30f, tm1=-1e30f;
        #pragma unroll
        for (int nt=0;nt<8;nt++){
            tm0 = fmaxf(tm0, fmaxf(s[nt][0], s[nt][1]));
            tm1 = fmaxf(tm1, fmaxf(s[nt][2], s[nt][3]));
        }
        tm0 = fmaxf(tm0, __shfl_xor_sync(0xffffffffu, tm0, 1));
        tm0 = fmaxf(tm0, __shfl_xor_sync(0xffffffffu, tm0, 2));
        tm1 = fmaxf(tm1, __shfl_xor_sync(0xffffffffu, tm1, 1));
        tm1 = fmaxf(tm1, __shfl_xor_sync(0xffffffffu, tm1, 2));
        float nm0 = fmaxf(m0, tm0), nm1 = fmaxf(m1, tm1);
        float cor0 = __expf(m0-nm0), cor1 = __expf(m1-nm1);
        m0 = nm0; m1 = nm1;
        float ts0 = 0.f, ts1 = 0.f;
        #pragma unroll
        for (int nt=0;nt<8;nt++){
            s[nt][0] = __expf(s[nt][0]-nm0); ts0 += s[nt][0];
            s[nt][1] = __expf(s[nt][1]-nm0); ts0 += s[nt][1];
            s[nt][2] = __expf(s[nt][2]-nm1); ts1 += s[nt][2];
            s[nt][3] = __expf(s[nt][3]-nm1); ts1 += s[nt][3];
        }
        ts0 += __shfl_xor_sync(0xffffffffu, ts0, 1);
        ts0 += __shfl_xor_sync(0xffffffffu, ts0, 2);
        ts1 += __shfl_xor_sync(0xffffffffu, ts1, 1);
        ts1 += __shfl_xor_sync(0xffffffffu, ts1, 2);
        l0 = l0*cor0 + ts0; l1 = l1*cor1 + ts1;
        #pragma unroll
        for (int dt=0;dt<8;dt++){
            o[dt][0]*=cor0; o[dt][1]*=cor0; o[dt][2]*=cor1; o[dt][3]*=cor1;
        }

        #pragma unroll
        for (int kc=0;kc<4;kc++){
            u32 ph_[4];
            ph_[0] = pack2h(s[2*kc][0],   s[2*kc][1]);
            ph_[1] = pack2h(s[2*kc][2],   s[2*kc][3]);
            ph_[2] = pack2h(s[2*kc+1][0], s[2*kc+1][1]);
            ph_[3] = pack2h(s[2*kc+1][2], s[2*kc+1][3]);
            #pragma unroll
            for (int dt=0;dt<8;dt++){
                int bi = (dt*8+g)*SK + kc*8 + c;
                u32 vh0 = Vph[bi], vh1 = Vph[bi+4];
                mma_f16(o[dt], ph_, vh0, vh1);
            }
        }
        __syncthreads();
    }

    float i0 = 1.f/l0, i1 = 1.f/l1;
    size_t yb0 = ((size_t)(b*T_SEQ) + Q0+wrow+g)*C_DIM + h*HD;
    size_t yb1 = yb0 + 8ull*C_DIM;
    #pragma unroll
    for (int dt=0;dt<8;dt++){
        int dc = dt*8 + 2*c;
        *(u32*)(g_yh+yb0+dc) = pack2h(o[dt][0]*i0, o[dt][1]*i0);
        *(u32*)(g_yh+yb1+dc) = pack2h(o[dt][2]*i1, o[dt][3]*i1);
    }
}

// ---------------------------------------------------------------------------
extern "C" void kernel_launch(void* const* d_in, const int* in_sizes, int n_in,
                              void* d_out, int out_size)
{
    (void)in_sizes; (void)n_in; (void)out_size;
    const float* x     = (const float*)d_in[0];
    const float* W_qkv = (const float*)d_in[2];
    const float* b_qkv = (const float*)d_in[3];
    const float* W_out = (const float*)d_in[4];
    const float* b_out = (const float*)d_in[5];
    float* out = (float*)d_out;

    gemm_kernel<0><<<dim3(N_QKV/128, 4096/128), 256>>>(x, W_qkv, b_qkv, nullptr);
    attn_kernel<<<dim3(B_SZ*NH, T_SEQ/128), 256>>>();
    gemm_kernel<1><<<dim3(C_DIM/128, 4096/128), 256>>>(nullptr, W_out, b_out, out);
}